// round 7
// baseline (speedup 1.0000x reference)
#include <cuda_runtime.h>

// B=512 rows, L=16 labels, N=8192 values. Single kernel, 512 blocks.
// loss = sum_l inv[l] * A_l,  inv[l] = 1/((np*nn)^2 * 256)
// A_l  = sum_{i pos, j neg} S[i,j],  S[i,j] = sum_{c,d} relu(1 - x[i,c] + x[j,d])
// Per j-row (16 values): sorted ascending xs[] + suffix sums suf[k]=sum_{m>=k}xs.
// Then sum_d relu(a + x_d) = (16-cnt)*a + suf[cnt],  cnt = #{x_d < -a}.
// Each block owns one j-tile (16 rows) and TWO i-tiles (32 rows); 1 thread per
// (i-row, j-row) pair per i-tile. Per-label partials -> ticketed last block.

#define NROW 512
#define NL   16
#define TI   16
#define NBLK 512                 // 32 j-tiles x 16 i-tile-pairs
#define ASP  257                 // padded stride, per-label scatter array
#define XSP  17                  // stride for xs / suf rows

__device__ float        g_inv[NL];
__device__ float        g_pl[NBLK * NL];
__device__ unsigned int g_cnt = 0;

__global__ void __launch_bounds__(256) k_all(const int* __restrict__ yt,
                                             const float* __restrict__ yp,
                                             float* __restrict__ out, int n_out) {
    __shared__ float    xi[2 * TI * NL];     // two i-tiles, row-major (512 floats)
    __shared__ float    xs [TI * XSP];       // sorted j-row values
    __shared__ float    suf[TI * XSP];       // suffix sums, 17 entries per row
    __shared__ float    As[NL * ASP];        // per-label scatter [l][tid]
    __shared__ float    A2[NL * 17];         // stage-2 partials [l][chunk]
    __shared__ float    wfin[NL];
    __shared__ unsigned pmI[2 * TI], nmJ[TI];
    __shared__ int      cnt_s[NL];
    __shared__ int      is_last;

    const int b   = blockIdx.x;
    const int bj  = b & 31;          // j-tile (0..31)
    const int bp  = b >> 5;          // i-tile pair (0..15) -> rows bp*32..bp*32+31
    const int tid = threadIdx.x;

    // ---- stage the two i-tiles ---------------------------------------------
    xi[tid]       = yp[bp * 512 + tid];
    xi[tid + 256] = yp[bp * 512 + 256 + tid];

    // ---- block 0: per-label n_pos -> g_inv ----------------------------------
    if (b == 0) {
        if (tid < NL) cnt_s[tid] = 0;
        __syncthreads();
        const int r0 = 2 * tid;
        unsigned m0 = 0, m1 = 0;
        const int4* y4 = (const int4*)(yt + r0 * NL);
        #pragma unroll
        for (int q = 0; q < 4; q++) {
            int4 v = y4[q];
            if (v.x) m0 |= 1u << (4 * q + 0);
            if (v.y) m0 |= 1u << (4 * q + 1);
            if (v.z) m0 |= 1u << (4 * q + 2);
            if (v.w) m0 |= 1u << (4 * q + 3);
        }
        #pragma unroll
        for (int q = 0; q < 4; q++) {
            int4 v = y4[4 + q];
            if (v.x) m1 |= 1u << (4 * q + 0);
            if (v.y) m1 |= 1u << (4 * q + 1);
            if (v.z) m1 |= 1u << (4 * q + 2);
            if (v.w) m1 |= 1u << (4 * q + 3);
        }
        #pragma unroll
        for (int l = 0; l < NL; l++) {
            unsigned b0 = __ballot_sync(0xffffffffu, (m0 >> l) & 1u);
            unsigned b1 = __ballot_sync(0xffffffffu, (m1 >> l) & 1u);
            if ((tid & 31) == 0) atomicAdd(&cnt_s[l], __popc(b0) + __popc(b1));
        }
        __syncthreads();
        if (tid < NL) {
            int np = cnt_s[tid], nn = NROW - np;
            float d = (float)np * (float)nn;           // <= 2^18, exact in fp32
            g_inv[tid] = (np > 0 && nn > 0) ? 1.0f / (d * d * 256.0f) : 0.0f;
        }
    }

    // ---- row masks: 32 i-rows + 16 j-rows ------------------------------------
    if (tid < 3 * TI) {
        int row = (tid < 2 * TI) ? (bp * 32 + tid) : (bj * TI + (tid - 2 * TI));
        unsigned m = 0;
        const int4* y4 = (const int4*)(yt + row * NL);
        #pragma unroll
        for (int q = 0; q < 4; q++) {
            int4 v = y4[q];
            if (v.x) m |= 1u << (4 * q + 0);
            if (v.y) m |= 1u << (4 * q + 1);
            if (v.z) m |= 1u << (4 * q + 2);
            if (v.w) m |= 1u << (4 * q + 3);
        }
        if (tid < 2 * TI) pmI[tid] = m;
        else              nmJ[tid - 2 * TI] = (~m) & 0xFFFFu;
    }

    // ---- sort each j-row (16 threads, register bitonic) + suffix sums --------
    if (tid < TI) {
        float v[TI];
        const float4* p4 = (const float4*)(yp + bj * 256 + tid * NL);
        #pragma unroll
        for (int q = 0; q < 4; q++) {
            float4 f = p4[q];
            v[4 * q] = f.x; v[4 * q + 1] = f.y; v[4 * q + 2] = f.z; v[4 * q + 3] = f.w;
        }
        #pragma unroll
        for (int k = 2; k <= 16; k <<= 1) {
            #pragma unroll
            for (int j = k >> 1; j > 0; j >>= 1) {
                #pragma unroll
                for (int i = 0; i < 16; i++) {
                    int ixj = i ^ j;
                    if (ixj > i) {
                        float lo = fminf(v[i], v[ixj]);
                        float hi = fmaxf(v[i], v[ixj]);
                        if ((i & k) == 0) { v[i] = lo; v[ixj] = hi; }
                        else              { v[i] = hi; v[ixj] = lo; }
                    }
                }
            }
        }
        float s = 0.0f;
        suf[tid * XSP + 16] = 0.0f;
        #pragma unroll
        for (int k = 15; k >= 0; k--) {
            xs[tid * XSP + k] = v[k];
            s += v[k];
            suf[tid * XSP + k] = s;
        }
    }
    __syncthreads();

    // ---- hot loop: two i-tiles, binary search per (c, j-row) -----------------
    const int il = tid >> 4;
    const int jl = tid & 15;
    const int jb = jl * XSP;

    float S0 = 0.0f, S1 = 0.0f;
    #pragma unroll
    for (int c = 0; c < NL; c++) {
        // tile 0
        {
            float xv  = xi[il * NL + c];
            float a   = 1.0f - xv;
            float key = xv - 1.0f;               // = -a
            int cnt = (xs[jb + 7] < key) ? 8 : 0;
            cnt += (xs[jb + cnt + 3] < key) ? 4 : 0;
            cnt += (xs[jb + cnt + 1] < key) ? 2 : 0;
            cnt += (xs[jb + cnt]     < key) ? 1 : 0;
            S0 += fmaf((float)(16 - cnt), a, suf[jb + cnt]);
        }
        // tile 1
        {
            float xv  = xi[256 + il * NL + c];
            float a   = 1.0f - xv;
            float key = xv - 1.0f;
            int cnt = (xs[jb + 7] < key) ? 8 : 0;
            cnt += (xs[jb + cnt + 3] < key) ? 4 : 0;
            cnt += (xs[jb + cnt + 1] < key) ? 2 : 0;
            cnt += (xs[jb + cnt]     < key) ? 1 : 0;
            S1 += fmaf((float)(16 - cnt), a, suf[jb + cnt]);
        }
    }

    // ---- per-label scatter (both tiles fused) + block reduction --------------
    unsigned mask0 = pmI[il]      & nmJ[jl];
    unsigned mask1 = pmI[16 + il] & nmJ[jl];
    #pragma unroll
    for (int l = 0; l < NL; l++) {
        float v = (((mask0 >> l) & 1u) ? S0 : 0.0f)
                + (((mask1 >> l) & 1u) ? S1 : 0.0f);
        As[l * ASP + tid] = v;
    }
    __syncthreads();

    {
        const int l = tid & 15, ch = tid >> 4;
        float a = 0.0f;
        #pragma unroll
        for (int k = 0; k < 16; k++) a += As[l * ASP + ch * 16 + k];
        A2[l * 17 + ch] = a;
    }
    __syncthreads();

    if (tid < NL) {
        float s = 0.0f;
        #pragma unroll
        for (int c = 0; c < 16; c++) s += A2[tid * 17 + c];
        g_pl[b * NL + tid] = s;
        __threadfence();
    }
    __syncthreads();

    if (tid == 0) {
        unsigned t = atomicAdd(&g_cnt, 1u);
        is_last = (t == NBLK - 1);
    }
    __syncthreads();

    // ---- last block: global per-label reduce + weighted combine --------------
    if (is_last) {
        __threadfence();
        const int l = tid & 15, ch = tid >> 4;
        float a = 0.0f;
        for (int k = 0; k < 32; k++)                    // fixed order: deterministic
            a += g_pl[(ch * 32 + k) * NL + l];
        A2[l * 17 + ch] = a;
        __syncthreads();
        if (tid < NL) {
            float s = 0.0f;
            #pragma unroll
            for (int c = 0; c < 16; c++) s += A2[tid * 17 + c];
            wfin[tid] = s * g_inv[tid];
        }
        __syncthreads();
        if (tid == 0) {
            float loss = 0.0f;
            #pragma unroll
            for (int l2 = 0; l2 < NL; l2++) loss += wfin[l2];
            out[0] = loss;
            g_cnt  = 0;                 // reset for next graph replay
        }
        for (int i = tid + 1; i < n_out; i += 256) out[i] = 0.0f;
    }
}

extern "C" void kernel_launch(void* const* d_in, const int* in_sizes, int n_in,
                              void* d_out, int out_size) {
    const int*   yt  = (const int*)d_in[0];    // y_true int32 [512*16]
    const float* yp  = (const float*)d_in[1];  // y_pred fp32  [512*16]
    float*       out = (float*)d_out;

    k_all<<<NBLK, 256>>>(yt, yp, out, out_size);
}